// round 1
// baseline (speedup 1.0000x reference)
#include <cuda_runtime.h>

// Problem constants (LightGCN_56538949484988)
#define NN 50000           // nodes
#define EE 800000          // edges
#define NCV (NN * 32)      // float4 elements per feature array (C=128 -> 32 float4/node)

// ---------------- device scratch (no allocations allowed) ----------------
__device__ int    g_is32;          // 1 if indices are int32, 0 if int64
__device__ int    g_deg[NN];
__device__ int    g_off[NN];
__device__ int    g_cur[NN];
__device__ int    g_col[EE];
__device__ float  g_dinv[NN];
__device__ float4 g_u0[NCV];       // u = dinv (.) h   (ping)
__device__ float4 g_u1[NCV];       // (pong)
__device__ float4 g_final[NCV];    // id_embed + h1 + h2 + h3

__device__ __forceinline__ int ld_idx(const void* p, long long i, int is32) {
    if (is32) return ((const int*)p)[i];
    return (int)((const long long*)p)[i];
}

// Detect whether index buffers are int32 or int64: read as int64; random int32
// pairs produce values >= NN with overwhelming probability.
__global__ void detect_kernel(const void* eidx, int n_check) {
    __shared__ int flag;
    if (threadIdx.x == 0) flag = 0;
    __syncthreads();
    const long long* p = (const long long*)eidx;
    for (int i = threadIdx.x; i < n_check; i += blockDim.x) {
        long long v = p[i];
        if (v < 0 || v >= (long long)NN) flag = 1;   // benign race
    }
    __syncthreads();
    if (threadIdx.x == 0) g_is32 = flag;
}

__global__ void zero_deg_kernel(int N) {
    int i = blockIdx.x * blockDim.x + threadIdx.x;
    if (i < N) g_deg[i] = 0;
}

__global__ void hist_kernel(const void* __restrict__ eidx, int E) {
    int e = blockIdx.x * blockDim.x + threadIdx.x;
    if (e >= E) return;
    int is32 = g_is32;
    int r = ld_idx(eidx, e, is32);
    atomicAdd(&g_deg[r], 1);
}

// Single-block exclusive scan over degrees -> offsets, cursors, dinv.
__global__ void scan_kernel(int N) {
    __shared__ int part[1024];
    int t = threadIdx.x;
    int chunk = (N + 1023) >> 10;
    int s = t * chunk;
    int e = min(s + chunk, N);
    int sum = 0;
    for (int i = s; i < e; i++) sum += g_deg[i];
    part[t] = sum;
    __syncthreads();
    for (int d = 1; d < 1024; d <<= 1) {
        int v = (t >= d) ? part[t - d] : 0;
        __syncthreads();
        part[t] += v;
        __syncthreads();
    }
    int base = (t > 0) ? part[t - 1] : 0;
    for (int i = s; i < e; i++) {
        g_off[i] = base;
        g_cur[i] = base;
        int dg = g_deg[i];
        base += dg;
        g_dinv[i] = (dg > 0) ? rsqrtf((float)dg) : 0.0f;
    }
}

__global__ void scatter_kernel(const void* __restrict__ eidx, int E) {
    int e = blockIdx.x * blockDim.x + threadIdx.x;
    if (e >= E) return;
    int is32 = g_is32;
    int r = ld_idx(eidx, e, is32);
    int c = ld_idx(eidx, (long long)E + e, is32);
    int p = atomicAdd(&g_cur[r], 1);
    g_col[p] = c;
}

// final = emb ; u0 = dinv (.) emb
__global__ void init_kernel(const float4* __restrict__ emb, int N) {
    int i = blockIdx.x * blockDim.x + threadIdx.x;
    if (i >= N * 32) return;
    float4 v = emb[i];
    g_final[i] = v;
    float di = g_dinv[i >> 5];
    float4 u;
    u.x = v.x * di; u.y = v.y * di; u.z = v.z * di; u.w = v.w * di;
    g_u0[i] = u;
}

// One propagation layer, warp-per-node pull gather (no atomics):
//   acc = sum_{c in N(i)} u_in[c]
//   h   = dinv[i] * acc ; final += h ; u_out = dinv[i] * h
__global__ __launch_bounds__(256) void prop_kernel(int layer, int N) {
    int gw   = (blockIdx.x * blockDim.x + threadIdx.x) >> 5;
    int lane = threadIdx.x & 31;
    if (gw >= N) return;
    const float4* __restrict__ uin  = (layer & 1) ? g_u1 : g_u0;
    float4* __restrict__       uout = (layer & 1) ? g_u0 : g_u1;
    int start = g_off[gw];
    int d     = g_deg[gw];
    float ax = 0.f, ay = 0.f, az = 0.f, aw = 0.f;
#pragma unroll 4
    for (int j = 0; j < d; j++) {
        int c = __ldg(&g_col[start + j]);
        float4 v = __ldg(&uin[(c << 5) + lane]);
        ax += v.x; ay += v.y; az += v.z; aw += v.w;
    }
    float di = g_dinv[gw];
    float hx = di * ax, hy = di * ay, hz = di * az, hw = di * aw;
    int idx = (gw << 5) + lane;
    float4 f = g_final[idx];
    f.x += hx; f.y += hy; f.z += hz; f.w += hw;
    g_final[idx] = f;
    float4 u;
    u.x = di * hx; u.y = di * hy; u.z = di * hz; u.w = di * hw;
    uout[idx] = u;
}

// Head: rows [0,b) = pos pairs, rows [b, 6b) = neg pairs.
// One warp computes 4 rows. z (256 floats/row, scaled by 1/4) lives in
// registers: lane l holds z[l*8 .. l*8+7]; broadcast via shfl.
// w1 (128 KB) read through __ldg -> L1-resident (zero smem used).
__global__ __launch_bounds__(256) void head_kernel(
    const void* __restrict__ nid,
    const float4* __restrict__ w1,     // [256][32] float4 view of (256,128)
    const float* __restrict__ b1,
    const float* __restrict__ w2,
    const float* __restrict__ b2,
    float* __restrict__ out,
    int b, int total)
{
    int lane = threadIdx.x & 31;
    int warp = (blockIdx.x * blockDim.x + threadIdx.x) >> 5;
    int row0 = warp * 4;
    if (row0 >= total) return;
    int is32 = g_is32;
    int nvalid = min(4, total - row0);

    float zr[4][8];
#pragma unroll
    for (int r = 0; r < 4; r++) {
        int row = row0 + ((r < nvalid) ? r : 0);   // clamp dups keep shfl well-defined
        int q, o;
        if (row < b) {
            q = ld_idx(nid, row, is32);
            o = ld_idx(nid, b + row, is32);
        } else {
            int j = row - b;
            q = ld_idx(nid, j / 5, is32);
            o = ld_idx(nid, 2 * b + j, is32);
        }
        int node = (lane < 16) ? q : o;
        int l = lane & 15;
        float4 a  = __ldg(&g_final[node * 32 + l * 2]);
        float4 bb = __ldg(&g_final[node * 32 + l * 2 + 1]);
        zr[r][0] = 0.25f * a.x;  zr[r][1] = 0.25f * a.y;
        zr[r][2] = 0.25f * a.z;  zr[r][3] = 0.25f * a.w;
        zr[r][4] = 0.25f * bb.x; zr[r][5] = 0.25f * bb.y;
        zr[r][6] = 0.25f * bb.z; zr[r][7] = 0.25f * bb.w;
    }

    float4 acc[4];
#pragma unroll
    for (int r = 0; r < 4; r++) { acc[r].x = acc[r].y = acc[r].z = acc[r].w = 0.f; }

    for (int k8 = 0; k8 < 32; k8++) {
#pragma unroll
        for (int s = 0; s < 8; s++) {
            int k = k8 * 8 + s;
            float4 wv = __ldg(&w1[k * 32 + lane]);
#pragma unroll
            for (int r = 0; r < 4; r++) {
                float zk = __shfl_sync(0xffffffffu, zr[r][s], k8);
                acc[r].x += zk * wv.x;
                acc[r].y += zk * wv.y;
                acc[r].z += zk * wv.z;
                acc[r].w += zk * wv.w;
            }
        }
    }

    float4 b1v = __ldg((const float4*)b1 + lane);
    float4 w2v = __ldg((const float4*)w2 + lane);
    float bias2 = __ldg(b2);
#pragma unroll
    for (int r = 0; r < 4; r++) {
        if (r >= nvalid) break;
        float4 h = acc[r];
        h.x += b1v.x; h.y += b1v.y; h.z += b1v.z; h.w += b1v.w;
        h.x = (h.x > 0.f) ? h.x : 0.2f * h.x;
        h.y = (h.y > 0.f) ? h.y : 0.2f * h.y;
        h.z = (h.z > 0.f) ? h.z : 0.2f * h.z;
        h.w = (h.w > 0.f) ? h.w : 0.2f * h.w;
        float p = h.x * w2v.x + h.y * w2v.y + h.z * w2v.z + h.w * w2v.w;
#pragma unroll
        for (int off = 16; off; off >>= 1) p += __shfl_xor_sync(0xffffffffu, p, off);
        if (lane == 0) out[row0 + r] = p + bias2;
    }
}

extern "C" void kernel_launch(void* const* d_in, const int* in_sizes, int n_in,
                              void* d_out, int out_size) {
    // Input order: x, edge_index, edge_weight, n_id, [neg_sample_num], id_embed, w1, b1, w2, b2
    const void* eidx = d_in[1];
    int E = in_sizes[1] / 2;
    const void* nid = d_in[3];
    int base = (n_in >= 10) ? 5 : 4;   // neg_sample_num may or may not be a buffer
    const float* emb = (const float*)d_in[base];
    const float* w1  = (const float*)d_in[base + 1];
    const float* b1  = (const float*)d_in[base + 2];
    const float* w2  = (const float*)d_in[base + 3];
    const float* b2  = (const float*)d_in[base + 4];
    int N = in_sizes[base] / 128;
    int b = in_sizes[3] / 7;           // (2 + NEG) parts
    int total = b * 6;                 // b pos rows + 5b neg rows
    float* out = (float*)d_out;
    (void)out_size;

    if (N > NN) N = NN;
    if (E > EE) E = EE;

    detect_kernel<<<1, 256>>>(eidx, 1024);
    zero_deg_kernel<<<(N + 255) / 256, 256>>>(N);
    hist_kernel<<<(E + 255) / 256, 256>>>(eidx, E);
    scan_kernel<<<1, 1024>>>(N);
    scatter_kernel<<<(E + 255) / 256, 256>>>(eidx, E);
    init_kernel<<<(N * 32 + 255) / 256, 256>>>((const float4*)emb, N);

    for (int layer = 0; layer < 3; layer++) {
        prop_kernel<<<(N + 7) / 8, 256>>>(layer, N);
    }

    int warps = (total + 3) / 4;
    head_kernel<<<(warps + 7) / 8, 256>>>(nid, (const float4*)w1, b1, w2, b2, out, b, total);
}

// round 2
// speedup vs baseline: 1.5195x; 1.5195x over previous
#include <cuda_runtime.h>

// Problem constants (LightGCN_56538949484988)
#define NN 50000           // nodes
#define EE 800000          // edges
#define NCV (NN * 32)      // float4 elements per feature array (C=128 -> 32 float4/node)
#define NBLK_MAX 64        // ceil(NN/1024) = 49

// ---------------- device scratch (no allocations allowed) ----------------
__device__ int    g_is32;          // 1 if indices are int32, 0 if int64
__device__ int    g_deg[NN];
__device__ int    g_off[NN];
__device__ int    g_cur[NN];
__device__ int    g_col[EE];
__device__ float  g_dinv[NN];
__device__ int    g_bsum[NBLK_MAX];
__device__ int    g_boff[NBLK_MAX];
__device__ float4 g_u0[NCV];       // u = dinv (.) h   (ping)
__device__ float4 g_u1[NCV];       // (pong)
__device__ float4 g_final[NCV];    // id_embed + h1 + h2 + h3

__device__ __forceinline__ int ld_idx(const void* p, long long i, int is32) {
    if (is32) return ((const int*)p)[i];
    return (int)((const long long*)p)[i];
}

// Detect whether index buffers are int32 or int64: read as int64; random int32
// pairs produce values >= NN with overwhelming probability.
__global__ void detect_kernel(const void* eidx, int n_check) {
    __shared__ int flag;
    if (threadIdx.x == 0) flag = 0;
    __syncthreads();
    const long long* p = (const long long*)eidx;
    for (int i = threadIdx.x; i < n_check; i += blockDim.x) {
        long long v = p[i];
        if (v < 0 || v >= (long long)NN) flag = 1;   // benign race
    }
    __syncthreads();
    if (threadIdx.x == 0) g_is32 = flag;
}

__global__ void zero_deg_kernel(int N) {
    int i = blockIdx.x * blockDim.x + threadIdx.x;
    if (i < N) g_deg[i] = 0;
}

__global__ void hist_kernel(const void* __restrict__ eidx, int E) {
    int e = blockIdx.x * blockDim.x + threadIdx.x;
    if (e >= E) return;
    int is32 = g_is32;
    int r = ld_idx(eidx, e, is32);
    atomicAdd(&g_deg[r], 1);
}

// ---- Multi-block scan, phase A: per-block (1024 elems) partial sums ----
__global__ __launch_bounds__(256) void scan_partial_kernel(int N) {
    __shared__ int ssum[8];
    int base = blockIdx.x * 1024;
    int t = threadIdx.x;
    int i0 = base + t * 4;
    int s = 0;
#pragma unroll
    for (int j = 0; j < 4; j++) {
        int i = i0 + j;
        if (i < N) s += g_deg[i];
    }
#pragma unroll
    for (int o = 16; o; o >>= 1) s += __shfl_xor_sync(0xffffffffu, s, o);
    if ((t & 31) == 0) ssum[t >> 5] = s;
    __syncthreads();
    if (t < 8) {
        int v = ssum[t];
#pragma unroll
        for (int o = 4; o; o >>= 1) v += __shfl_xor_sync(0x000000ffu, v, o);
        if (t == 0) g_bsum[blockIdx.x] = v;
    }
}

// ---- phase B: exclusive scan of <=64 block sums (one 64-thread block) ----
__global__ void scan_bsum_kernel(int nblk) {
    __shared__ int wtot[2];
    int t = threadIdx.x;              // blockDim = 64
    int v = (t < nblk) ? g_bsum[t] : 0;
    int lane = t & 31, w = t >> 5;
    int x = v;
#pragma unroll
    for (int o = 1; o < 32; o <<= 1) {
        int y = __shfl_up_sync(0xffffffffu, x, o);
        if (lane >= o) x += y;
    }
    if (lane == 31) wtot[w] = x;
    __syncthreads();
    int add = (w == 1) ? wtot[0] : 0;
    if (t < nblk) g_boff[t] = x - v + add;   // exclusive prefix
}

// ---- phase C: local exclusive scan + block offset -> off/cur/dinv ----
__global__ __launch_bounds__(256) void scan_final_kernel(int N) {
    __shared__ int wsum[8];
    int base = blockIdx.x * 1024;
    int t = threadIdx.x;
    int i0 = base + t * 4;
    int d0 = 0, d1 = 0, d2 = 0, d3 = 0;
    if (i0 + 0 < N) d0 = g_deg[i0 + 0];
    if (i0 + 1 < N) d1 = g_deg[i0 + 1];
    if (i0 + 2 < N) d2 = g_deg[i0 + 2];
    if (i0 + 3 < N) d3 = g_deg[i0 + 3];
    int tsum = d0 + d1 + d2 + d3;
    int lane = t & 31, w = t >> 5;
    int x = tsum;
#pragma unroll
    for (int o = 1; o < 32; o <<= 1) {
        int y = __shfl_up_sync(0xffffffffu, x, o);
        if (lane >= o) x += y;
    }
    if (lane == 31) wsum[w] = x;
    __syncthreads();
    int wpref = 0;
#pragma unroll
    for (int j = 0; j < 8; j++) if (j < w) wpref += wsum[j];
    int excl = x - tsum + wpref + g_boff[blockIdx.x];
    int o0 = excl, o1 = o0 + d0, o2 = o1 + d1, o3 = o2 + d2;
    if (i0 + 0 < N) { g_off[i0+0] = o0; g_cur[i0+0] = o0; g_dinv[i0+0] = d0 > 0 ? rsqrtf((float)d0) : 0.f; }
    if (i0 + 1 < N) { g_off[i0+1] = o1; g_cur[i0+1] = o1; g_dinv[i0+1] = d1 > 0 ? rsqrtf((float)d1) : 0.f; }
    if (i0 + 2 < N) { g_off[i0+2] = o2; g_cur[i0+2] = o2; g_dinv[i0+2] = d2 > 0 ? rsqrtf((float)d2) : 0.f; }
    if (i0 + 3 < N) { g_off[i0+3] = o3; g_cur[i0+3] = o3; g_dinv[i0+3] = d3 > 0 ? rsqrtf((float)d3) : 0.f; }
}

__global__ void scatter_kernel(const void* __restrict__ eidx, int E) {
    int e = blockIdx.x * blockDim.x + threadIdx.x;
    if (e >= E) return;
    int is32 = g_is32;
    int r = ld_idx(eidx, e, is32);
    int c = ld_idx(eidx, (long long)E + e, is32);
    int p = atomicAdd(&g_cur[r], 1);
    g_col[p] = c;
}

// final = emb ; u0 = dinv (.) emb
__global__ void init_kernel(const float4* __restrict__ emb, int N) {
    int i = blockIdx.x * blockDim.x + threadIdx.x;
    if (i >= N * 32) return;
    float4 v = emb[i];
    g_final[i] = v;
    float di = g_dinv[i >> 5];
    float4 u;
    u.x = v.x * di; u.y = v.y * di; u.z = v.z * di; u.w = v.w * di;
    g_u0[i] = u;
}

// One propagation layer, warp-per-node pull gather (no atomics):
//   acc = sum_{c in N(i)} u_in[c]
//   h   = dinv[i] * acc ; final += h ; u_out = dinv[i] * h (skipped on last layer)
__global__ __launch_bounds__(256) void prop_kernel(int layer, int N, int write_u) {
    int gw   = (blockIdx.x * blockDim.x + threadIdx.x) >> 5;
    int lane = threadIdx.x & 31;
    if (gw >= N) return;
    const float4* __restrict__ uin  = (layer & 1) ? g_u1 : g_u0;
    float4* __restrict__       uout = (layer & 1) ? g_u0 : g_u1;
    int start = g_off[gw];
    int d     = g_deg[gw];
    float ax = 0.f, ay = 0.f, az = 0.f, aw = 0.f;
#pragma unroll 4
    for (int j = 0; j < d; j++) {
        int c = __ldg(&g_col[start + j]);
        float4 v = __ldg(&uin[(c << 5) + lane]);
        ax += v.x; ay += v.y; az += v.z; aw += v.w;
    }
    float di = g_dinv[gw];
    float hx = di * ax, hy = di * ay, hz = di * az, hw = di * aw;
    int idx = (gw << 5) + lane;
    float4 f = g_final[idx];
    f.x += hx; f.y += hy; f.z += hz; f.w += hw;
    g_final[idx] = f;
    if (write_u) {
        float4 u;
        u.x = di * hx; u.y = di * hy; u.z = di * hz; u.w = di * hw;
        uout[idx] = u;
    }
}

// Head: rows [0,b) = pos pairs, rows [b, 6b) = neg pairs.
// One warp computes 4 rows. z (256 floats/row, scaled by 1/4) lives in
// registers: lane l holds z[l*8 .. l*8+7]; broadcast via shfl.
// w1 (128 KB) read through __ldg -> L1-resident (zero smem used).
__global__ __launch_bounds__(256) void head_kernel(
    const void* __restrict__ nid,
    const float4* __restrict__ w1,     // [256][32] float4 view of (256,128)
    const float* __restrict__ b1,
    const float* __restrict__ w2,
    const float* __restrict__ b2,
    float* __restrict__ out,
    int b, int total)
{
    int lane = threadIdx.x & 31;
    int warp = (blockIdx.x * blockDim.x + threadIdx.x) >> 5;
    int row0 = warp * 4;
    if (row0 >= total) return;
    int is32 = g_is32;
    int nvalid = min(4, total - row0);

    float zr[4][8];
#pragma unroll
    for (int r = 0; r < 4; r++) {
        int row = row0 + ((r < nvalid) ? r : 0);   // clamp dups keep shfl well-defined
        int q, o;
        if (row < b) {
            q = ld_idx(nid, row, is32);
            o = ld_idx(nid, b + row, is32);
        } else {
            int j = row - b;
            q = ld_idx(nid, j / 5, is32);
            o = ld_idx(nid, 2 * b + j, is32);
        }
        int node = (lane < 16) ? q : o;
        int l = lane & 15;
        float4 a  = __ldg(&g_final[node * 32 + l * 2]);
        float4 bb = __ldg(&g_final[node * 32 + l * 2 + 1]);
        zr[r][0] = 0.25f * a.x;  zr[r][1] = 0.25f * a.y;
        zr[r][2] = 0.25f * a.z;  zr[r][3] = 0.25f * a.w;
        zr[r][4] = 0.25f * bb.x; zr[r][5] = 0.25f * bb.y;
        zr[r][6] = 0.25f * bb.z; zr[r][7] = 0.25f * bb.w;
    }

    float4 acc[4];
#pragma unroll
    for (int r = 0; r < 4; r++) { acc[r].x = acc[r].y = acc[r].z = acc[r].w = 0.f; }

    for (int k8 = 0; k8 < 32; k8++) {
#pragma unroll
        for (int s = 0; s < 8; s++) {
            int k = k8 * 8 + s;
            float4 wv = __ldg(&w1[k * 32 + lane]);
#pragma unroll
            for (int r = 0; r < 4; r++) {
                float zk = __shfl_sync(0xffffffffu, zr[r][s], k8);
                acc[r].x += zk * wv.x;
                acc[r].y += zk * wv.y;
                acc[r].z += zk * wv.z;
                acc[r].w += zk * wv.w;
            }
        }
    }

    float4 b1v = __ldg((const float4*)b1 + lane);
    float4 w2v = __ldg((const float4*)w2 + lane);
    float bias2 = __ldg(b2);
#pragma unroll
    for (int r = 0; r < 4; r++) {
        if (r >= nvalid) break;
        float4 h = acc[r];
        h.x += b1v.x; h.y += b1v.y; h.z += b1v.z; h.w += b1v.w;
        h.x = (h.x > 0.f) ? h.x : 0.2f * h.x;
        h.y = (h.y > 0.f) ? h.y : 0.2f * h.y;
        h.z = (h.z > 0.f) ? h.z : 0.2f * h.z;
        h.w = (h.w > 0.f) ? h.w : 0.2f * h.w;
        float p = h.x * w2v.x + h.y * w2v.y + h.z * w2v.z + h.w * w2v.w;
#pragma unroll
        for (int off = 16; off; off >>= 1) p += __shfl_xor_sync(0xffffffffu, p, off);
        if (lane == 0) out[row0 + r] = p + bias2;
    }
}

extern "C" void kernel_launch(void* const* d_in, const int* in_sizes, int n_in,
                              void* d_out, int out_size) {
    // Input order: x, edge_index, edge_weight, n_id, [neg_sample_num], id_embed, w1, b1, w2, b2
    const void* eidx = d_in[1];
    int E = in_sizes[1] / 2;
    const void* nid = d_in[3];
    int base = (n_in >= 10) ? 5 : 4;   // neg_sample_num may or may not be a buffer
    const float* emb = (const float*)d_in[base];
    const float* w1  = (const float*)d_in[base + 1];
    const float* b1  = (const float*)d_in[base + 2];
    const float* w2  = (const float*)d_in[base + 3];
    const float* b2  = (const float*)d_in[base + 4];
    int N = in_sizes[base] / 128;
    int b = in_sizes[3] / 7;           // (2 + NEG) parts
    int total = b * 6;                 // b pos rows + 5b neg rows
    float* out = (float*)d_out;
    (void)out_size;

    if (N > NN) N = NN;
    if (E > EE) E = EE;

    int nblk = (N + 1023) / 1024;      // <= 49

    detect_kernel<<<1, 256>>>(eidx, 1024);
    zero_deg_kernel<<<(N + 255) / 256, 256>>>(N);
    hist_kernel<<<(E + 255) / 256, 256>>>(eidx, E);
    scan_partial_kernel<<<nblk, 256>>>(N);
    scan_bsum_kernel<<<1, 64>>>(nblk);
    scan_final_kernel<<<nblk, 256>>>(N);
    scatter_kernel<<<(E + 255) / 256, 256>>>(eidx, E);
    init_kernel<<<(N * 32 + 255) / 256, 256>>>((const float4*)emb, N);

    for (int layer = 0; layer < 3; layer++) {
        prop_kernel<<<(N + 7) / 8, 256>>>(layer, N, layer < 2);
    }

    int warps = (total + 3) / 4;
    head_kernel<<<(warps + 7) / 8, 256>>>(nid, (const float4*)w1, b1, w2, b2, out, b, total);
}

// round 3
// speedup vs baseline: 1.8960x; 1.2478x over previous
#include <cuda_runtime.h>
#include <cuda_fp16.h>

// Problem constants (LightGCN_56538949484988)
#define NN 50000           // nodes
#define EE 800000          // edges
#define NCV (NN * 32)      // float4 elems per fp32 feature array (C=128)
#define NBLK_MAX 64        // ceil(NN/1024) = 49

// ---------------- device scratch (no allocations allowed) ----------------
__device__ int    g_is32;          // 1 if indices are int32, 0 if int64
__device__ int    g_deg[NN];
__device__ int    g_off[NN];
__device__ int    g_cur[NN];
__device__ int    g_col[EE];
__device__ float  g_dinv[NN];
__device__ int    g_bsum[NBLK_MAX];
__device__ int    g_boff[NBLK_MAX];
__device__ uint2  g_u0[NCV];       // fp16 u = dinv (.) h  (ping)  [4 halves/elem]
__device__ uint2  g_u1[NCV];       // (pong)
__device__ float4 g_final[NCV];    // fp32: id_embed + h1 + h2 + h3

__device__ __forceinline__ int ld_idx(const void* p, long long i, int is32) {
    if (is32) return ((const int*)p)[i];
    return (int)((const long long*)p)[i];
}

__device__ __forceinline__ uint2 pack4h(float a, float b, float c, float d) {
    __half2 lo = __floats2half2_rn(a, b);
    __half2 hi = __floats2half2_rn(c, d);
    uint2 r;
    r.x = *reinterpret_cast<unsigned*>(&lo);
    r.y = *reinterpret_cast<unsigned*>(&hi);
    return r;
}

// Detect whether index buffers are int32 or int64.
__global__ void detect_kernel(const void* eidx, int n_check) {
    __shared__ int flag;
    if (threadIdx.x == 0) flag = 0;
    __syncthreads();
    const long long* p = (const long long*)eidx;
    for (int i = threadIdx.x; i < n_check; i += blockDim.x) {
        long long v = p[i];
        if (v < 0 || v >= (long long)NN) flag = 1;   // benign race
    }
    __syncthreads();
    if (threadIdx.x == 0) g_is32 = flag;
}

__global__ void zero_deg_kernel(int N) {
    int i = blockIdx.x * blockDim.x + threadIdx.x;
    if (i < N) g_deg[i] = 0;
}

__global__ void hist_kernel(const void* __restrict__ eidx, int E) {
    int e = blockIdx.x * blockDim.x + threadIdx.x;
    if (e >= E) return;
    int is32 = g_is32;
    int r = ld_idx(eidx, e, is32);
    atomicAdd(&g_deg[r], 1);
}

// ---- Multi-block scan, phase A: per-block (1024 elems) partial sums ----
__global__ __launch_bounds__(256) void scan_partial_kernel(int N) {
    __shared__ int ssum[8];
    int base = blockIdx.x * 1024;
    int t = threadIdx.x;
    int i0 = base + t * 4;
    int s = 0;
#pragma unroll
    for (int j = 0; j < 4; j++) {
        int i = i0 + j;
        if (i < N) s += g_deg[i];
    }
#pragma unroll
    for (int o = 16; o; o >>= 1) s += __shfl_xor_sync(0xffffffffu, s, o);
    if ((t & 31) == 0) ssum[t >> 5] = s;
    __syncthreads();
    if (t < 8) {
        int v = ssum[t];
#pragma unroll
        for (int o = 4; o; o >>= 1) v += __shfl_xor_sync(0x000000ffu, v, o);
        if (t == 0) g_bsum[blockIdx.x] = v;
    }
}

// ---- phase B: exclusive scan of <=64 block sums ----
__global__ void scan_bsum_kernel(int nblk) {
    __shared__ int wtot[2];
    int t = threadIdx.x;              // blockDim = 64
    int v = (t < nblk) ? g_bsum[t] : 0;
    int lane = t & 31, w = t >> 5;
    int x = v;
#pragma unroll
    for (int o = 1; o < 32; o <<= 1) {
        int y = __shfl_up_sync(0xffffffffu, x, o);
        if (lane >= o) x += y;
    }
    if (lane == 31) wtot[w] = x;
    __syncthreads();
    int add = (w == 1) ? wtot[0] : 0;
    if (t < nblk) g_boff[t] = x - v + add;   // exclusive prefix
}

// ---- phase C: local exclusive scan + block offset -> off/cur/dinv ----
__global__ __launch_bounds__(256) void scan_final_kernel(int N) {
    __shared__ int wsum[8];
    int base = blockIdx.x * 1024;
    int t = threadIdx.x;
    int i0 = base + t * 4;
    int d0 = 0, d1 = 0, d2 = 0, d3 = 0;
    if (i0 + 0 < N) d0 = g_deg[i0 + 0];
    if (i0 + 1 < N) d1 = g_deg[i0 + 1];
    if (i0 + 2 < N) d2 = g_deg[i0 + 2];
    if (i0 + 3 < N) d3 = g_deg[i0 + 3];
    int tsum = d0 + d1 + d2 + d3;
    int lane = t & 31, w = t >> 5;
    int x = tsum;
#pragma unroll
    for (int o = 1; o < 32; o <<= 1) {
        int y = __shfl_up_sync(0xffffffffu, x, o);
        if (lane >= o) x += y;
    }
    if (lane == 31) wsum[w] = x;
    __syncthreads();
    int wpref = 0;
#pragma unroll
    for (int j = 0; j < 8; j++) if (j < w) wpref += wsum[j];
    int excl = x - tsum + wpref + g_boff[blockIdx.x];
    int o0 = excl, o1 = o0 + d0, o2 = o1 + d1, o3 = o2 + d2;
    if (i0 + 0 < N) { g_off[i0+0] = o0; g_cur[i0+0] = o0; g_dinv[i0+0] = d0 > 0 ? rsqrtf((float)d0) : 0.f; }
    if (i0 + 1 < N) { g_off[i0+1] = o1; g_cur[i0+1] = o1; g_dinv[i0+1] = d1 > 0 ? rsqrtf((float)d1) : 0.f; }
    if (i0 + 2 < N) { g_off[i0+2] = o2; g_cur[i0+2] = o2; g_dinv[i0+2] = d2 > 0 ? rsqrtf((float)d2) : 0.f; }
    if (i0 + 3 < N) { g_off[i0+3] = o3; g_cur[i0+3] = o3; g_dinv[i0+3] = d3 > 0 ? rsqrtf((float)d3) : 0.f; }
}

__global__ void scatter_kernel(const void* __restrict__ eidx, int E) {
    int e = blockIdx.x * blockDim.x + threadIdx.x;
    if (e >= E) return;
    int is32 = g_is32;
    int r = ld_idx(eidx, e, is32);
    int c = ld_idx(eidx, (long long)E + e, is32);
    int p = atomicAdd(&g_cur[r], 1);
    g_col[p] = c;
}

// final = emb ; u0 = fp16(dinv (.) emb)
__global__ void init_kernel(const float4* __restrict__ emb, int N) {
    int i = blockIdx.x * blockDim.x + threadIdx.x;
    if (i >= N * 32) return;
    float4 v = emb[i];
    g_final[i] = v;
    float di = g_dinv[i >> 5];
    g_u0[i] = pack4h(v.x * di, v.y * di, v.z * di, v.w * di);
}

// One propagation layer, warp-per-node pull gather (no atomics), fp16 u:
//   acc = sum_{c in N(i)} u_in[c]   (fp32 accumulate)
//   h   = dinv[i] * acc ; final += h ; u_out = fp16(dinv[i] * h)
__global__ __launch_bounds__(256) void prop_kernel(int layer, int N, int write_u) {
    int gw   = (blockIdx.x * blockDim.x + threadIdx.x) >> 5;
    int lane = threadIdx.x & 31;
    if (gw >= N) return;
    const uint2* __restrict__ uin  = (layer & 1) ? g_u1 : g_u0;
    uint2* __restrict__       uout = (layer & 1) ? g_u0 : g_u1;
    int start = g_off[gw];
    int d     = g_deg[gw];
    float ax = 0.f, ay = 0.f, az = 0.f, aw = 0.f;
#pragma unroll 4
    for (int j = 0; j < d; j++) {
        int c = __ldg(&g_col[start + j]);
        uint2 v = __ldg(&uin[(c << 5) + lane]);
        __half2 lo = *reinterpret_cast<__half2*>(&v.x);
        __half2 hi = *reinterpret_cast<__half2*>(&v.y);
        float2 f0 = __half22float2(lo);
        float2 f1 = __half22float2(hi);
        ax += f0.x; ay += f0.y; az += f1.x; aw += f1.y;
    }
    float di = g_dinv[gw];
    float hx = di * ax, hy = di * ay, hz = di * az, hw = di * aw;
    int idx = (gw << 5) + lane;
    float4 f = g_final[idx];
    f.x += hx; f.y += hy; f.z += hz; f.w += hw;
    g_final[idx] = f;
    if (write_u) {
        uout[idx] = pack4h(di * hx, di * hy, di * hz, di * hw);
    }
}

// Head: rows [0,b) = pos pairs, rows [b, 6b) = neg pairs.
// One warp computes 4 rows; z in registers broadcast via shfl; w1 via __ldg (L1).
__global__ __launch_bounds__(256) void head_kernel(
    const void* __restrict__ nid,
    const float4* __restrict__ w1,     // [256][32] float4 view of (256,128)
    const float* __restrict__ b1,
    const float* __restrict__ w2,
    const float* __restrict__ b2,
    float* __restrict__ out,
    int b, int total)
{
    int lane = threadIdx.x & 31;
    int warp = (blockIdx.x * blockDim.x + threadIdx.x) >> 5;
    int row0 = warp * 4;
    if (row0 >= total) return;
    int is32 = g_is32;
    int nvalid = min(4, total - row0);

    float zr[4][8];
#pragma unroll
    for (int r = 0; r < 4; r++) {
        int row = row0 + ((r < nvalid) ? r : 0);   // clamp dups keep shfl well-defined
        int q, o;
        if (row < b) {
            q = ld_idx(nid, row, is32);
            o = ld_idx(nid, b + row, is32);
        } else {
            int j = row - b;
            q = ld_idx(nid, j / 5, is32);
            o = ld_idx(nid, 2 * b + j, is32);
        }
        int node = (lane < 16) ? q : o;
        int l = lane & 15;
        float4 a  = __ldg(&g_final[node * 32 + l * 2]);
        float4 bb = __ldg(&g_final[node * 32 + l * 2 + 1]);
        zr[r][0] = 0.25f * a.x;  zr[r][1] = 0.25f * a.y;
        zr[r][2] = 0.25f * a.z;  zr[r][3] = 0.25f * a.w;
        zr[r][4] = 0.25f * bb.x; zr[r][5] = 0.25f * bb.y;
        zr[r][6] = 0.25f * bb.z; zr[r][7] = 0.25f * bb.w;
    }

    float4 acc[4];
#pragma unroll
    for (int r = 0; r < 4; r++) { acc[r].x = acc[r].y = acc[r].z = acc[r].w = 0.f; }

    for (int k8 = 0; k8 < 32; k8++) {
#pragma unroll
        for (int s = 0; s < 8; s++) {
            int k = k8 * 8 + s;
            float4 wv = __ldg(&w1[k * 32 + lane]);
#pragma unroll
            for (int r = 0; r < 4; r++) {
                float zk = __shfl_sync(0xffffffffu, zr[r][s], k8);
                acc[r].x += zk * wv.x;
                acc[r].y += zk * wv.y;
                acc[r].z += zk * wv.z;
                acc[r].w += zk * wv.w;
            }
        }
    }

    float4 b1v = __ldg((const float4*)b1 + lane);
    float4 w2v = __ldg((const float4*)w2 + lane);
    float bias2 = __ldg(b2);
#pragma unroll
    for (int r = 0; r < 4; r++) {
        if (r >= nvalid) break;
        float4 h = acc[r];
        h.x += b1v.x; h.y += b1v.y; h.z += b1v.z; h.w += b1v.w;
        h.x = (h.x > 0.f) ? h.x : 0.2f * h.x;
        h.y = (h.y > 0.f) ? h.y : 0.2f * h.y;
        h.z = (h.z > 0.f) ? h.z : 0.2f * h.z;
        h.w = (h.w > 0.f) ? h.w : 0.2f * h.w;
        float p = h.x * w2v.x + h.y * w2v.y + h.z * w2v.z + h.w * w2v.w;
#pragma unroll
        for (int off = 16; off; off >>= 1) p += __shfl_xor_sync(0xffffffffu, p, off);
        if (lane == 0) out[row0 + r] = p + bias2;
    }
}

extern "C" void kernel_launch(void* const* d_in, const int* in_sizes, int n_in,
                              void* d_out, int out_size) {
    // Input order: x, edge_index, edge_weight, n_id, [neg_sample_num], id_embed, w1, b1, w2, b2
    const void* eidx = d_in[1];
    int E = in_sizes[1] / 2;
    const void* nid = d_in[3];
    int base = (n_in >= 10) ? 5 : 4;   // neg_sample_num may or may not be a buffer
    const float* emb = (const float*)d_in[base];
    const float* w1  = (const float*)d_in[base + 1];
    const float* b1  = (const float*)d_in[base + 2];
    const float* w2  = (const float*)d_in[base + 3];
    const float* b2  = (const float*)d_in[base + 4];
    int N = in_sizes[base] / 128;
    int b = in_sizes[3] / 7;           // (2 + NEG) parts
    int total = b * 6;                 // b pos rows + 5b neg rows
    float* out = (float*)d_out;
    (void)out_size;

    if (N > NN) N = NN;
    if (E > EE) E = EE;

    int nblk = (N + 1023) / 1024;      // <= 49

    detect_kernel<<<1, 256>>>(eidx, 1024);
    zero_deg_kernel<<<(N + 255) / 256, 256>>>(N);
    hist_kernel<<<(E + 255) / 256, 256>>>(eidx, E);
    scan_partial_kernel<<<nblk, 256>>>(N);
    scan_bsum_kernel<<<1, 64>>>(nblk);
    scan_final_kernel<<<nblk, 256>>>(N);
    scatter_kernel<<<(E + 255) / 256, 256>>>(eidx, E);
    init_kernel<<<(N * 32 + 255) / 256, 256>>>((const float4*)emb, N);

    for (int layer = 0; layer < 3; layer++) {
        prop_kernel<<<(N + 7) / 8, 256>>>(layer, N, layer < 2);
    }

    int warps = (total + 3) / 4;
    head_kernel<<<(warps + 7) / 8, 256>>>(nid, (const float4*)w1, b1, w2, b2, out, b, total);
}

// round 4
// speedup vs baseline: 2.1896x; 1.1549x over previous
#include <cuda_runtime.h>
#include <cuda_fp16.h>

// Problem constants (LightGCN_56538949484988)
#define NN 50000           // nodes
#define EE 800000          // edges
#define B_MAX 4096         // batch
#define ROWS7_MAX (7 * B_MAX)
#define NBLK_MAX 64        // ceil(NN/1024) = 49

// ---------------- device scratch (no allocations allowed) ----------------
__device__ int    g_is32;
__device__ int    g_deg[NN];
__device__ int    g_off[NN];
__device__ int    g_cur[NN];
__device__ int    g_col[EE];
__device__ float  g_dinv[NN];      // rsqrt(deg) or 0
__device__ float  g_sdeg[NN];      // sqrt(deg)
__device__ int    g_bsum[NBLK_MAX];
__device__ int    g_boff[NBLK_MAX];
// u_k = dinv^2 * (gathered sum) in fp16; h_k = u_k * sdeg.  16 uint4 per node row.
__device__ uint4  g_u0[NN * 16];
__device__ uint4  g_u1[NN * 16];
__device__ uint4  g_u2[NN * 16];
__device__ uint4  g_u3[NN * 16];
// phase-1 head output: t[i] = z_i @ W1half  (fp32, 128 per row)
__device__ float4 g_t[ROWS7_MAX * 32];

__device__ __forceinline__ int ld_idx(const void* p, long long i, int is32) {
    if (is32) return ((const int*)p)[i];
    return (int)((const long long*)p)[i];
}

__device__ __forceinline__ uint4 pack8h(const float* f) {
    __half2 h0 = __floats2half2_rn(f[0], f[1]);
    __half2 h1 = __floats2half2_rn(f[2], f[3]);
    __half2 h2 = __floats2half2_rn(f[4], f[5]);
    __half2 h3 = __floats2half2_rn(f[6], f[7]);
    uint4 r;
    r.x = *reinterpret_cast<unsigned*>(&h0);
    r.y = *reinterpret_cast<unsigned*>(&h1);
    r.z = *reinterpret_cast<unsigned*>(&h2);
    r.w = *reinterpret_cast<unsigned*>(&h3);
    return r;
}

// Detect int32 vs int64 indices.
__global__ void detect_kernel(const void* eidx, int n_check) {
    __shared__ int flag;
    if (threadIdx.x == 0) flag = 0;
    __syncthreads();
    const long long* p = (const long long*)eidx;
    for (int i = threadIdx.x; i < n_check; i += blockDim.x) {
        long long v = p[i];
        if (v < 0 || v >= (long long)NN) flag = 1;
    }
    __syncthreads();
    if (threadIdx.x == 0) g_is32 = flag;
}

__global__ void zero_deg_kernel(int N) {
    int i = blockIdx.x * blockDim.x + threadIdx.x;
    if (i < N) g_deg[i] = 0;
}

__global__ void hist_kernel(const void* __restrict__ eidx, int E) {
    int e = blockIdx.x * blockDim.x + threadIdx.x;
    if (e >= E) return;
    int r = ld_idx(eidx, e, g_is32);
    atomicAdd(&g_deg[r], 1);
}

// ---- scan phase A ----
__global__ __launch_bounds__(256) void scan_partial_kernel(int N) {
    __shared__ int ssum[8];
    int base = blockIdx.x * 1024;
    int t = threadIdx.x;
    int i0 = base + t * 4;
    int s = 0;
#pragma unroll
    for (int j = 0; j < 4; j++) {
        int i = i0 + j;
        if (i < N) s += g_deg[i];
    }
#pragma unroll
    for (int o = 16; o; o >>= 1) s += __shfl_xor_sync(0xffffffffu, s, o);
    if ((t & 31) == 0) ssum[t >> 5] = s;
    __syncthreads();
    if (t < 8) {
        int v = ssum[t];
#pragma unroll
        for (int o = 4; o; o >>= 1) v += __shfl_xor_sync(0x000000ffu, v, o);
        if (t == 0) g_bsum[blockIdx.x] = v;
    }
}

// ---- scan phase B ----
__global__ void scan_bsum_kernel(int nblk) {
    __shared__ int wtot[2];
    int t = threadIdx.x;              // 64 threads
    int v = (t < nblk) ? g_bsum[t] : 0;
    int lane = t & 31, w = t >> 5;
    int x = v;
#pragma unroll
    for (int o = 1; o < 32; o <<= 1) {
        int y = __shfl_up_sync(0xffffffffu, x, o);
        if (lane >= o) x += y;
    }
    if (lane == 31) wtot[w] = x;
    __syncthreads();
    int add = (w == 1) ? wtot[0] : 0;
    if (t < nblk) g_boff[t] = x - v + add;
}

// ---- scan phase C ----
__global__ __launch_bounds__(256) void scan_final_kernel(int N) {
    __shared__ int wsum[8];
    int base = blockIdx.x * 1024;
    int t = threadIdx.x;
    int i0 = base + t * 4;
    int d0 = 0, d1 = 0, d2 = 0, d3 = 0;
    if (i0 + 0 < N) d0 = g_deg[i0 + 0];
    if (i0 + 1 < N) d1 = g_deg[i0 + 1];
    if (i0 + 2 < N) d2 = g_deg[i0 + 2];
    if (i0 + 3 < N) d3 = g_deg[i0 + 3];
    int tsum = d0 + d1 + d2 + d3;
    int lane = t & 31, w = t >> 5;
    int x = tsum;
#pragma unroll
    for (int o = 1; o < 32; o <<= 1) {
        int y = __shfl_up_sync(0xffffffffu, x, o);
        if (lane >= o) x += y;
    }
    if (lane == 31) wsum[w] = x;
    __syncthreads();
    int wpref = 0;
#pragma unroll
    for (int j = 0; j < 8; j++) if (j < w) wpref += wsum[j];
    int excl = x - tsum + wpref + g_boff[blockIdx.x];
    int o0 = excl, o1 = o0 + d0, o2 = o1 + d1, o3 = o2 + d2;
#define EMIT(ii, oo, dd) \
    if (ii < N) { g_off[ii] = oo; g_cur[ii] = oo; \
        g_dinv[ii] = (dd) > 0 ? rsqrtf((float)(dd)) : 0.f; \
        g_sdeg[ii] = sqrtf((float)(dd)); }
    EMIT(i0 + 0, o0, d0)
    EMIT(i0 + 1, o1, d1)
    EMIT(i0 + 2, o2, d2)
    EMIT(i0 + 3, o3, d3)
#undef EMIT
}

__global__ void scatter_kernel(const void* __restrict__ eidx, int E) {
    int e = blockIdx.x * blockDim.x + threadIdx.x;
    if (e >= E) return;
    int is32 = g_is32;
    int r = ld_idx(eidx, e, is32);
    int c = ld_idx(eidx, (long long)E + e, is32);
    int p = atomicAdd(&g_cur[r], 1);
    g_col[p] = c;
}

// u0 = fp16(dinv (.) emb)    (i over N*16, each handles 8 floats)
__global__ void init_kernel(const float4* __restrict__ emb, int N) {
    int i = blockIdx.x * blockDim.x + threadIdx.x;
    if (i >= N * 16) return;
    int node = i >> 4, p = i & 15;
    float4 a = emb[node * 32 + p * 2];
    float4 b = emb[node * 32 + p * 2 + 1];
    float di = g_dinv[node];
    float f[8] = { a.x * di, a.y * di, a.z * di, a.w * di,
                   b.x * di, b.y * di, b.z * di, b.w * di };
    g_u0[i] = pack8h(f);
}

// One layer: warp per node; half-warps process 2 edges/trip; 16 lanes x uint4 per row.
//   acc = sum_c u_in[c]  (fp32);  u_out = dinv^2 * acc  (fp16)
__global__ __launch_bounds__(256) void prop_kernel(int layer, int N) {
    int gw   = (blockIdx.x * blockDim.x + threadIdx.x) >> 5;
    int lane = threadIdx.x & 31;
    if (gw >= N) return;
    const uint4* __restrict__ uin  = (layer == 0) ? g_u0 : (layer == 1) ? g_u1 : g_u2;
    uint4* __restrict__       uout = (layer == 0) ? g_u1 : (layer == 1) ? g_u2 : g_u3;
    int start = g_off[gw];
    int end   = start + g_deg[gw];
    int half  = lane >> 4;
    int l16   = lane & 15;
    float a[8] = {0.f, 0.f, 0.f, 0.f, 0.f, 0.f, 0.f, 0.f};
#pragma unroll 4
    for (int e = start + half; e < end; e += 2) {
        int c = __ldg(&g_col[e]);
        uint4 v = __ldg(&uin[c * 16 + l16]);
        __half2 h0 = *reinterpret_cast<__half2*>(&v.x);
        __half2 h1 = *reinterpret_cast<__half2*>(&v.y);
        __half2 h2 = *reinterpret_cast<__half2*>(&v.z);
        __half2 h3 = *reinterpret_cast<__half2*>(&v.w);
        float2 f0 = __half22float2(h0); a[0] += f0.x; a[1] += f0.y;
        float2 f1 = __half22float2(h1); a[2] += f1.x; a[3] += f1.y;
        float2 f2 = __half22float2(h2); a[4] += f2.x; a[5] += f2.y;
        float2 f3 = __half22float2(h3); a[6] += f3.x; a[7] += f3.y;
    }
#pragma unroll
    for (int i = 0; i < 8; i++) a[i] += __shfl_xor_sync(0xffffffffu, a[i], 16);
    float di = g_dinv[gw];
    float s = di * di;
    if (half == 0) {
        float f[8];
#pragma unroll
        for (int i = 0; i < 8; i++) f[i] = s * a[i];
        uout[gw * 16 + l16] = pack8h(f);
    }
}

// Head phase 1: t[i] = z_i @ W1half for all 7b n_id rows.
//   z_i = 0.25*(emb[node] + sdeg[node]*(u1+u2+u3)[node])   (128 floats)
//   rows i < b use W1top (k 0..127), else W1bot (k 128..255).
// Warp computes 4 rows x 128 outputs; z in regs (4/lane), shfl-broadcast.
__global__ __launch_bounds__(256) void head1_kernel(
    const void* __restrict__ nid,
    const float4* __restrict__ emb,
    const float4* __restrict__ w1,     // (256,128) row-major, float4 view
    int b, int rows7)
{
    int lane = threadIdx.x & 31;
    int warp = (blockIdx.x * blockDim.x + threadIdx.x) >> 5;
    int row0 = warp * 4;
    if (row0 >= rows7) return;
    int is32 = g_is32;
    int nvalid = min(4, rows7 - row0);

    const uint2* u1v = reinterpret_cast<const uint2*>(g_u1);
    const uint2* u2v = reinterpret_cast<const uint2*>(g_u2);
    const uint2* u3v = reinterpret_cast<const uint2*>(g_u3);

    float zr[4][4];
    int koffr[4];
#pragma unroll
    for (int r = 0; r < 4; r++) {
        int row = row0 + ((r < nvalid) ? r : (nvalid - 1));
        koffr[r] = (row < b) ? 0 : 128;
        int node = ld_idx(nid, row, is32);
        float4 e = __ldg(&emb[node * 32 + lane]);
        uint2 v1 = __ldg(&u1v[node * 32 + lane]);
        uint2 v2 = __ldg(&u2v[node * 32 + lane]);
        uint2 v3 = __ldg(&u3v[node * 32 + lane]);
        float sd = __ldg(&g_sdeg[node]);
        float2 a0 = __half22float2(*reinterpret_cast<__half2*>(&v1.x));
        float2 a1 = __half22float2(*reinterpret_cast<__half2*>(&v1.y));
        float2 b0 = __half22float2(*reinterpret_cast<__half2*>(&v2.x));
        float2 b1_ = __half22float2(*reinterpret_cast<__half2*>(&v2.y));
        float2 c0 = __half22float2(*reinterpret_cast<__half2*>(&v3.x));
        float2 c1 = __half22float2(*reinterpret_cast<__half2*>(&v3.y));
        zr[r][0] = 0.25f * (e.x + sd * (a0.x + b0.x + c0.x));
        zr[r][1] = 0.25f * (e.y + sd * (a0.y + b0.y + c0.y));
        zr[r][2] = 0.25f * (e.z + sd * (a1.x + b1_.x + c1.x));
        zr[r][3] = 0.25f * (e.w + sd * (a1.y + b1_.y + c1.y));
    }

    float4 acc[4];
#pragma unroll
    for (int r = 0; r < 4; r++) { acc[r].x = acc[r].y = acc[r].z = acc[r].w = 0.f; }

    bool uni = (koffr[0] == koffr[3]);
    if (uni) {
        int koff = koffr[0];
        for (int k4 = 0; k4 < 32; k4++) {
#pragma unroll
            for (int s = 0; s < 4; s++) {
                int k = k4 * 4 + s;
                float4 wv = __ldg(&w1[(koff + k) * 32 + lane]);
#pragma unroll
                for (int r = 0; r < 4; r++) {
                    float zk = __shfl_sync(0xffffffffu, zr[r][s], k4);
                    acc[r].x += zk * wv.x;
                    acc[r].y += zk * wv.y;
                    acc[r].z += zk * wv.z;
                    acc[r].w += zk * wv.w;
                }
            }
        }
    } else {
        for (int k4 = 0; k4 < 32; k4++) {
#pragma unroll
            for (int s = 0; s < 4; s++) {
                int k = k4 * 4 + s;
#pragma unroll
                for (int r = 0; r < 4; r++) {
                    float4 wv = __ldg(&w1[(koffr[r] + k) * 32 + lane]);
                    float zk = __shfl_sync(0xffffffffu, zr[r][s], k4);
                    acc[r].x += zk * wv.x;
                    acc[r].y += zk * wv.y;
                    acc[r].z += zk * wv.z;
                    acc[r].w += zk * wv.w;
                }
            }
        }
    }

#pragma unroll
    for (int r = 0; r < 4; r++) {
        if (r >= nvalid) break;
        g_t[(row0 + r) * 32 + lane] = acc[r];
    }
}

// Head phase 2: logits.
//   row < b (pos):   h = t[row] + t[b+row] + b1
//   row >= b (neg):  j = row-b; h = t[j/5] + t[2b+j] + b1
//   out[row] = leaky(h) . w2 + b2
__global__ __launch_bounds__(256) void head2_kernel(
    const float* __restrict__ b1,
    const float* __restrict__ w2,
    const float* __restrict__ b2,
    float* __restrict__ out,
    int b, int total)
{
    int lane = threadIdx.x & 31;
    int warp = (blockIdx.x * blockDim.x + threadIdx.x) >> 5;
    int row0 = warp * 4;
    if (row0 >= total) return;
    float4 b1v = __ldg((const float4*)b1 + lane);
    float4 w2v = __ldg((const float4*)w2 + lane);
    float bias2 = __ldg(b2);
    int nvalid = min(4, total - row0);
    for (int r = 0; r < nvalid; r++) {
        int row = row0 + r;
        int i1, i2;
        if (row < b) { i1 = row; i2 = b + row; }
        else { int j = row - b; i1 = j / 5; i2 = 2 * b + j; }
        float4 ta = __ldg(&g_t[i1 * 32 + lane]);
        float4 tb = __ldg(&g_t[i2 * 32 + lane]);
        float4 h;
        h.x = ta.x + tb.x + b1v.x;
        h.y = ta.y + tb.y + b1v.y;
        h.z = ta.z + tb.z + b1v.z;
        h.w = ta.w + tb.w + b1v.w;
        h.x = (h.x > 0.f) ? h.x : 0.2f * h.x;
        h.y = (h.y > 0.f) ? h.y : 0.2f * h.y;
        h.z = (h.z > 0.f) ? h.z : 0.2f * h.z;
        h.w = (h.w > 0.f) ? h.w : 0.2f * h.w;
        float p = h.x * w2v.x + h.y * w2v.y + h.z * w2v.z + h.w * w2v.w;
#pragma unroll
        for (int off = 16; off; off >>= 1) p += __shfl_xor_sync(0xffffffffu, p, off);
        if (lane == 0) out[row] = p + bias2;
    }
}

extern "C" void kernel_launch(void* const* d_in, const int* in_sizes, int n_in,
                              void* d_out, int out_size) {
    // Order: x, edge_index, edge_weight, n_id, [neg_sample_num], id_embed, w1, b1, w2, b2
    const void* eidx = d_in[1];
    int E = in_sizes[1] / 2;
    const void* nid = d_in[3];
    int base = (n_in >= 10) ? 5 : 4;
    const float* emb = (const float*)d_in[base];
    const float* w1  = (const float*)d_in[base + 1];
    const float* b1  = (const float*)d_in[base + 2];
    const float* w2  = (const float*)d_in[base + 3];
    const float* b2  = (const float*)d_in[base + 4];
    int N = in_sizes[base] / 128;
    int b = in_sizes[3] / 7;
    if (b > B_MAX) b = B_MAX;
    int rows7 = b * 7;
    int total = b * 6;
    float* out = (float*)d_out;
    (void)out_size;

    if (N > NN) N = NN;
    if (E > EE) E = EE;

    int nblk = (N + 1023) / 1024;

    detect_kernel<<<1, 256>>>(eidx, 1024);
    zero_deg_kernel<<<(N + 255) / 256, 256>>>(N);
    hist_kernel<<<(E + 255) / 256, 256>>>(eidx, E);
    scan_partial_kernel<<<nblk, 256>>>(N);
    scan_bsum_kernel<<<1, 64>>>(nblk);
    scan_final_kernel<<<nblk, 256>>>(N);
    scatter_kernel<<<(E + 255) / 256, 256>>>(eidx, E);
    init_kernel<<<(N * 16 + 255) / 256, 256>>>((const float4*)emb, N);

    for (int layer = 0; layer < 3; layer++) {
        prop_kernel<<<(N + 7) / 8, 256>>>(layer, N);
    }

    int w1blocks = ((rows7 + 3) / 4 + 7) / 8;
    head1_kernel<<<w1blocks, 256>>>(nid, (const float4*)emb, (const float4*)w1, b, rows7);
    int w2blocks = ((total + 3) / 4 + 7) / 8;
    head2_kernel<<<w2blocks, 256>>>(b1, w2, b2, out, b, total);
}